// round 9
// baseline (speedup 1.0000x reference)
#include <cuda_runtime.h>
#include <cuda_fp16.h>
#include <cstdint>

// ============================================================
// Fused GRUCell, sm_103 base-PTX (ldmatrix + mma.sync.m16n8k16).
// A-fragments (x, hx) built directly from global memory with
// sector-efficient LDG.64; hx fragments reused for r*hx and the
// epilogue. SMEM holds only weights + biases. 128-thread CTAs,
// 3 CTAs/SM (12 warps) for latency cover; n packed to fp16 after
// its GEMMs to cap register pressure; L2 prefetch of next slab.
//   r = sig(x@Wir + hx@Whr + br); z = sig(x@Wiz + hx@Whz + bz)
//   n = tanh(x@Win + (r*hx)@Whn + bn); h = hx + z*(n - hx)
// B = 1048576, H = 64. M = 32 rows per warp per iteration.
// ============================================================

#define DEV __device__ __forceinline__

static constexpr int NSLAB = 1048576 / 32;       // 32768 slabs of 32 rows

// ---- dynamic SMEM layout (bytes) ----
static constexpr int OFF_W    = 0;               // 6 x [64x64] f16 SW128 rows = 49152
static constexpr int OFF_BIAS = 49152;           // 3 x 64 fp32 = 768
static constexpr int SMEM_SZ  = 50176;

DEV uint32_t sw(uint32_t o) { return o ^ ((o >> 3) & 0x70); }

DEV uint32_t s2u(const void* p) {
    uint32_t a;
    asm("{ .reg .u64 t; cvta.to.shared.u64 t, %1; cvt.u32.u64 %0, t; }" : "=r"(a) : "l"(p));
    return a;
}

DEV void pf_l2(const void* p) {
    asm volatile("prefetch.global.L2 [%0];" :: "l"(p));
}

DEV void ldsm4t(uint32_t& d0, uint32_t& d1, uint32_t& d2, uint32_t& d3, uint32_t a) {
    asm volatile("ldmatrix.sync.aligned.m8n8.x4.trans.shared.b16 {%0,%1,%2,%3}, [%4];"
                 : "=r"(d0), "=r"(d1), "=r"(d2), "=r"(d3) : "r"(a));
}

DEV void mma4(float* c, const uint32_t* a, uint32_t b0, uint32_t b1) {
    asm volatile(
        "mma.sync.aligned.m16n8k16.row.col.f32.f16.f16.f32 "
        "{%0,%1,%2,%3}, {%4,%5,%6,%7}, {%8,%9}, {%0,%1,%2,%3};"
        : "+f"(c[0]), "+f"(c[1]), "+f"(c[2]), "+f"(c[3])
        : "r"(a[0]), "r"(a[1]), "r"(a[2]), "r"(a[3]), "r"(b0), "r"(b1));
}

// single-MUFU activations
DEV float tanh_ap(float x) {
    float r;
    asm("tanh.approx.f32 %0, %1;" : "=f"(r) : "f"(x));
    return r;
}
DEV float sigm(float x) { return fmaf(0.5f, tanh_ap(0.5f * x), 0.5f); }

DEV uint32_t packh2(float a, float b) {
    __half2 h = __floats2half2_rn(a, b);
    return *(uint32_t*)&h;
}

// GEMM accumulate: acc[2][8][4] += A(32x64 reg frags) @ W(64x64 f16 smem)
DEV void gemm2(float acc[2][8][4], const uint32_t af[2][4][4], uint32_t wbase, int laneB) {
    #pragma unroll
    for (int kb = 0; kb < 4; kb++) {
        #pragma unroll
        for (int nbp = 0; nbp < 4; nbp++) {
            uint32_t b0, b1, b2, b3;
            ldsm4t(b0, b1, b2, b3, wbase + sw((uint32_t)(laneB + kb * 2048 + nbp * 32)));
            #pragma unroll
            for (int mb = 0; mb < 2; mb++) {
                mma4(acc[mb][2 * nbp],     af[mb][kb], b0, b1);
                mma4(acc[mb][2 * nbp + 1], af[mb][kb], b2, b3);
            }
        }
    }
}

__global__ void __launch_bounds__(128, 3) gru_kernel(
    const float* __restrict__ x,    const float* __restrict__ hx,
    const float* __restrict__ w_ir, const float* __restrict__ w_hr,
    const float* __restrict__ w_iz, const float* __restrict__ w_hz,
    const float* __restrict__ w_in, const float* __restrict__ w_hn,
    const float* __restrict__ b_r,  const float* __restrict__ b_z,
    const float* __restrict__ b_n,  float* __restrict__ out)
{
    extern __shared__ char sm[];
    const uint32_t SB = s2u(sm);
    const int tid  = threadIdx.x;
    const int lane = tid & 31;
    const int wid  = tid >> 5;             // 0..3

    // ---- one-time: weights -> f16 SMEM ([k][n] rows of 128B, SW128), biases ----
    {
        const float* ws[6] = {w_ir, w_hr, w_iz, w_hz, w_in, w_hn};
        #pragma unroll 1
        for (int g = 0; g < 6; g++) {
            const float* w = ws[g];
            for (int i = tid; i < 4096; i += 128) {
                int k = i >> 6, n = i & 63;
                *(__half*)(sm + OFF_W + g * 8192 + sw((uint32_t)(k * 128 + n * 2))) =
                    __float2half_rn(w[i]);
            }
        }
        if (tid < 64) {
            float* bs = (float*)(sm + OFF_BIAS);
            bs[tid]       = b_r[tid];
            bs[64 + tid]  = b_z[tid];
            bs[128 + tid] = b_n[tid];
        }
    }
    __syncthreads();   // only CTA-wide barrier in the kernel

    const int laneB = (lane & 15) * 128 + ((lane >> 4) << 4);  // ldmatrix B lane offset
    const int q2    = (lane & 3) * 2;
    const int grow  = lane >> 2;

    const long stride = 4L * gridDim.x;

    for (long g = (long)blockIdx.x * 4 + wid; g < NSLAB; g += stride) {
        // ---- L2 prefetch of next slab (zero register cost) ----
        {
            const long gp = g + stride;
            if (gp < NSLAB) {
                const char* px = (const char*)(x  + (size_t)gp * 2048) + lane * 256;
                const char* ph = (const char*)(hx + (size_t)gp * 2048) + lane * 256;
                pf_l2(px); pf_l2(px + 128);
                pf_l2(ph); pf_l2(ph + 128);
            }
        }

        // ---- build A-fragments for x and hx straight from gmem ----
        // frag a0:(grow, c..c+1) a1:(grow+8, c..) a2:(grow, c+8..) a3:(grow+8, c+8..)
        uint32_t xf[2][4][4], hf[2][4][4];
        {
            const float* xb = x  + (size_t)g * 2048;   // 32 rows x 64
            const float* hb = hx + (size_t)g * 2048;
            #pragma unroll
            for (int mb = 0; mb < 2; mb++) {
                const float* xr0 = xb + (mb * 16 + grow) * 64;
                const float* xr8 = xr0 + 8 * 64;
                const float* hr0 = hb + (mb * 16 + grow) * 64;
                const float* hr8 = hr0 + 8 * 64;
                #pragma unroll
                for (int kb = 0; kb < 4; kb++) {
                    int c = kb * 16 + q2;
                    float2 v0 = *(const float2*)(xr0 + c);
                    float2 v1 = *(const float2*)(xr8 + c);
                    float2 v2 = *(const float2*)(xr0 + c + 8);
                    float2 v3 = *(const float2*)(xr8 + c + 8);
                    xf[mb][kb][0] = packh2(v0.x, v0.y);
                    xf[mb][kb][1] = packh2(v1.x, v1.y);
                    xf[mb][kb][2] = packh2(v2.x, v2.y);
                    xf[mb][kb][3] = packh2(v3.x, v3.y);
                    float2 u0 = *(const float2*)(hr0 + c);
                    float2 u1 = *(const float2*)(hr8 + c);
                    float2 u2 = *(const float2*)(hr0 + c + 8);
                    float2 u3 = *(const float2*)(hr8 + c + 8);
                    hf[mb][kb][0] = packh2(u0.x, u0.y);
                    hf[mb][kb][1] = packh2(u1.x, u1.y);
                    hf[mb][kb][2] = packh2(u2.x, u2.y);
                    hf[mb][kb][3] = packh2(u3.x, u3.y);
                }
            }
        }

        // ---- r = sig(x@Wir + hx@Whr + br) ----
        float rc[2][8][4];
        #pragma unroll
        for (int nb = 0; nb < 8; nb++) {
            float2 br = *(float2*)(sm + OFF_BIAS + (nb * 8 + q2) * 4);
            #pragma unroll
            for (int mb = 0; mb < 2; mb++) {
                rc[mb][nb][0] = br.x; rc[mb][nb][1] = br.y;
                rc[mb][nb][2] = br.x; rc[mb][nb][3] = br.y;
            }
        }
        gemm2(rc, xf, SB + OFF_W,            laneB);
        gemm2(rc, hf, SB + OFF_W + 1 * 8192, laneB);

        // ---- rh = sigmoid(rc) * hx -> A-fragments (hx from hf, fp16) ----
        uint32_t rhf[2][4][4];
        #pragma unroll
        for (int mb = 0; mb < 2; mb++) {
            #pragma unroll
            for (int kb = 0; kb < 4; kb++) {
                const float* ce = rc[mb][2 * kb];
                const float* co = rc[mb][2 * kb + 1];
                __half2 s0 = __floats2half2_rn(sigm(ce[0]), sigm(ce[1]));
                __half2 s1 = __floats2half2_rn(sigm(ce[2]), sigm(ce[3]));
                __half2 s2 = __floats2half2_rn(sigm(co[0]), sigm(co[1]));
                __half2 s3 = __floats2half2_rn(sigm(co[2]), sigm(co[3]));
                __half2 m0 = __hmul2(s0, *(const __half2*)&hf[mb][kb][0]);
                __half2 m1 = __hmul2(s1, *(const __half2*)&hf[mb][kb][1]);
                __half2 m2 = __hmul2(s2, *(const __half2*)&hf[mb][kb][2]);
                __half2 m3 = __hmul2(s3, *(const __half2*)&hf[mb][kb][3]);
                rhf[mb][kb][0] = *(uint32_t*)&m0;
                rhf[mb][kb][1] = *(uint32_t*)&m1;
                rhf[mb][kb][2] = *(uint32_t*)&m2;
                rhf[mb][kb][3] = *(uint32_t*)&m3;
            }
        }

        // ---- n = x@Win + rh@Whn + bn (rc dead) ----
        float nc[2][8][4];
        #pragma unroll
        for (int nb = 0; nb < 8; nb++) {
            float2 bn = *(float2*)(sm + OFF_BIAS + 512 + (nb * 8 + q2) * 4);
            #pragma unroll
            for (int mb = 0; mb < 2; mb++) {
                nc[mb][nb][0] = bn.x; nc[mb][nb][1] = bn.y;
                nc[mb][nb][2] = bn.x; nc[mb][nb][3] = bn.y;
            }
        }
        gemm2(nc, xf,  SB + OFF_W + 4 * 8192, laneB);
        gemm2(nc, rhf, SB + OFF_W + 5 * 8192, laneB);

        // ---- pack n = tanh(nc) to fp16 (64 fp32 -> 32 regs; rhf, nc die) ----
        uint32_t nt[2][8][2];
        #pragma unroll
        for (int mb = 0; mb < 2; mb++) {
            #pragma unroll
            for (int nb = 0; nb < 8; nb++) {
                const float* nn = nc[mb][nb];
                nt[mb][nb][0] = packh2(tanh_ap(nn[0]), tanh_ap(nn[1]));  // row grow
                nt[mb][nb][1] = packh2(tanh_ap(nn[2]), tanh_ap(nn[3]));  // row grow+8
            }
        }

        // ---- z = sig(x@Wiz + hx@Whz + bz) ----
        float zc[2][8][4];
        #pragma unroll
        for (int nb = 0; nb < 8; nb++) {
            float2 bz = *(float2*)(sm + OFF_BIAS + 256 + (nb * 8 + q2) * 4);
            #pragma unroll
            for (int mb = 0; mb < 2; mb++) {
                zc[mb][nb][0] = bz.x; zc[mb][nb][1] = bz.y;
                zc[mb][nb][2] = bz.x; zc[mb][nb][3] = bz.y;
            }
        }
        gemm2(zc, xf, SB + OFF_W + 2 * 8192, laneB);
        gemm2(zc, hf, SB + OFF_W + 3 * 8192, laneB);

        // ---- epilogue: h = hx + z*(n - hx); hx from hf, n from nt ----
        #pragma unroll
        for (int mb = 0; mb < 2; mb++) {
            const long rg = g * 32 + mb * 16 + grow;
            #pragma unroll
            for (int nb = 0; nb < 8; nb++) {
                int kb = nb >> 1, e = (nb & 1) * 2;
                float2 a = __half22float2(*(const __half2*)&hf[mb][kb][e]);     // row grow
                float2 b = __half22float2(*(const __half2*)&hf[mb][kb][e + 1]); // row grow+8
                float2 na = __half22float2(*(const __half2*)&nt[mb][nb][0]);
                float2 nb2 = __half22float2(*(const __half2*)&nt[mb][nb][1]);
                const float* zz = zc[mb][nb];
                float z0 = sigm(zz[0]), z1 = sigm(zz[1]);
                float z2 = sigm(zz[2]), z3 = sigm(zz[3]);
                *(float2*)(out + rg * 64 + (nb * 8 + q2)) =
                    make_float2(fmaf(z0, na.x - a.x, a.x), fmaf(z1, na.y - a.y, a.y));
                *(float2*)(out + (rg + 8) * 64 + (nb * 8 + q2)) =
                    make_float2(fmaf(z2, nb2.x - b.x, b.x), fmaf(z3, nb2.y - b.y, b.y));
            }
        }
    }
}

extern "C" void kernel_launch(void* const* d_in, const int* in_sizes, int n_in,
                              void* d_out, int out_size) {
    int sms = 0;
    cudaDeviceGetAttribute(&sms, cudaDevAttrMultiProcessorCount, 0);
    if (sms <= 0) sms = 148;
    cudaFuncSetAttribute(gru_kernel, cudaFuncAttributeMaxDynamicSharedMemorySize, SMEM_SZ);
    gru_kernel<<<sms * 3, 128, SMEM_SZ>>>(
        (const float*)d_in[0], (const float*)d_in[1],
        (const float*)d_in[2], (const float*)d_in[3],
        (const float*)d_in[4], (const float*)d_in[5],
        (const float*)d_in[6], (const float*)d_in[7],
        (const float*)d_in[8], (const float*)d_in[9],
        (const float*)d_in[10], (float*)d_out);
}

// round 10
// speedup vs baseline: 1.7381x; 1.7381x over previous
#include <cuda_runtime.h>
#include <cuda_fp16.h>
#include <cstdint>

// ============================================================
// Fused GRUCell, sm_103 base-PTX (ldmatrix + mma.sync.m16n8k16).
// K- and N-permuted weight layout in SMEM so that:
//   * A-fragments (x, hx) load as one LDG.128 float4 per lane
//   * epilogue writes STG.128 (4 consecutive cols per lane)
//   * r*hx fragment identity and hx epilogue reuse keep R7's code
// SMEM holds only weights + biases (all permuted). M = 32 rows
// per warp, 256-thread CTAs, 1 CTA/SM, grid-stride slabs.
//   r = sig(x@Wir + hx@Whr + br); z = sig(x@Wiz + hx@Whz + bz)
//   n = tanh(x@Win + (r*hx)@Whn + bn); h = hx + z*(n - hx)
// B = 1048576, H = 64.
// ============================================================

#define DEV __device__ __forceinline__

static constexpr int NSLAB = 1048576 / 32;       // 32768 slabs of 32 rows

// ---- dynamic SMEM layout (bytes) ----
static constexpr int OFF_W    = 0;               // 6 x [64x64] f16 SW128 rows = 49152
static constexpr int OFF_BIAS = 49152;           // 3 x 64 fp32 = 768
static constexpr int SMEM_SZ  = 50176;

DEV uint32_t sw(uint32_t o) { return o ^ ((o >> 3) & 0x70); }

DEV uint32_t s2u(const void* p) {
    uint32_t a;
    asm("{ .reg .u64 t; cvta.to.shared.u64 t, %1; cvt.u32.u64 %0, t; }" : "=r"(a) : "l"(p));
    return a;
}

DEV void pf_l2(const void* p) {
    asm volatile("prefetch.global.L2 [%0];" :: "l"(p));
}

DEV void ldsm4t(uint32_t& d0, uint32_t& d1, uint32_t& d2, uint32_t& d3, uint32_t a) {
    asm volatile("ldmatrix.sync.aligned.m8n8.x4.trans.shared.b16 {%0,%1,%2,%3}, [%4];"
                 : "=r"(d0), "=r"(d1), "=r"(d2), "=r"(d3) : "r"(a));
}

DEV void mma4(float* c, const uint32_t* a, uint32_t b0, uint32_t b1) {
    asm volatile(
        "mma.sync.aligned.m16n8k16.row.col.f32.f16.f16.f32 "
        "{%0,%1,%2,%3}, {%4,%5,%6,%7}, {%8,%9}, {%0,%1,%2,%3};"
        : "+f"(c[0]), "+f"(c[1]), "+f"(c[2]), "+f"(c[3])
        : "r"(a[0]), "r"(a[1]), "r"(a[2]), "r"(a[3]), "r"(b0), "r"(b1));
}

// single-MUFU activations
DEV float tanh_ap(float x) {
    float r;
    asm("tanh.approx.f32 %0, %1;" : "=f"(r) : "f"(x));
    return r;
}
DEV float sigm(float x) { return fmaf(0.5f, tanh_ap(0.5f * x), 0.5f); }

DEV uint32_t packh2(float a, float b) {
    __half2 h = __floats2half2_rn(a, b);
    return *(uint32_t*)&h;
}

// GEMM accumulate: acc[2][8][4] += A(32x64 reg frags) @ W(64x64 f16 smem)
DEV void gemm2(float acc[2][8][4], const uint32_t af[2][4][4], uint32_t wbase, int laneB) {
    #pragma unroll
    for (int kb = 0; kb < 4; kb++) {
        #pragma unroll
        for (int nbp = 0; nbp < 4; nbp++) {
            uint32_t b0, b1, b2, b3;
            ldsm4t(b0, b1, b2, b3, wbase + sw((uint32_t)(laneB + kb * 2048 + nbp * 32)));
            #pragma unroll
            for (int mb = 0; mb < 2; mb++) {
                mma4(acc[mb][2 * nbp],     af[mb][kb], b0, b1);
                mma4(acc[mb][2 * nbp + 1], af[mb][kb], b2, b3);
            }
        }
    }
}

__global__ void __launch_bounds__(256, 1) gru_kernel(
    const float* __restrict__ x,    const float* __restrict__ hx,
    const float* __restrict__ w_ir, const float* __restrict__ w_hr,
    const float* __restrict__ w_iz, const float* __restrict__ w_hz,
    const float* __restrict__ w_in, const float* __restrict__ w_hn,
    const float* __restrict__ b_r,  const float* __restrict__ b_z,
    const float* __restrict__ b_n,  float* __restrict__ out)
{
    extern __shared__ char sm[];
    const uint32_t SB = s2u(sm);
    const int tid  = threadIdx.x;
    const int lane = tid & 31;
    const int wid  = tid >> 5;

    // ---- one-time: weights -> f16 SMEM, K-rows and N-cols permuted ----
    // K row perm (per 16-block):  krow(k) = 2*((k>>2)&3) + (k&1) + ((k&2)<<2)
    //   (mma K-slot kappa holds physical x-col p with kappa(p) = this map)
    // N col perm sigma^-1 (per 16-block): pos(n) = ((n&2)<<2) | ((n>>1)&6) | (n&1)
    //   (C-fragment position j holds output col sigma(j); lane t owns 4
    //    consecutive output cols kb*16+4t..+3 -> STG.128 epilogue)
    {
        const float* ws[6] = {w_ir, w_hr, w_iz, w_hz, w_in, w_hn};
        #pragma unroll 1
        for (int g = 0; g < 6; g++) {
            const float* w = ws[g];
            for (int i = tid; i < 4096; i += 256) {
                int k = i >> 6, n = i & 63;
                int krow = (k & 48) | (2 * ((k >> 2) & 3) + (k & 1) + ((k & 2) << 2));
                int ncol = (n & 48) | ((n & 2) << 2) | ((n >> 1) & 6) | (n & 1);
                *(__half*)(sm + OFF_W + g * 8192 + sw((uint32_t)(krow * 128 + ncol * 2))) =
                    __float2half_rn(w[i]);
            }
        }
        if (tid < 64) {
            // bias position j holds b[sigma(j)]
            int m = ((tid >> 4) << 4) | ((tid & 6) << 1) | (((tid >> 3) & 1) << 1) | (tid & 1);
            float* bs = (float*)(sm + OFF_BIAS);
            bs[tid]       = b_r[m];
            bs[64 + tid]  = b_z[m];
            bs[128 + tid] = b_n[m];
        }
    }
    __syncthreads();   // only CTA-wide barrier in the kernel

    const int laneB = (lane & 15) * 128 + ((lane >> 4) << 4);  // ldmatrix B lane offset
    const int q2    = (lane & 3) * 2;
    const int t4    = (lane & 3) * 4;
    const int grow  = lane >> 2;

    const long stride = 8L * gridDim.x;

    for (long g = (long)blockIdx.x * 8 + wid; g < NSLAB; g += stride) {
        // ---- L2 prefetch of next slab ----
        {
            const long gp = g + stride;
            if (gp < NSLAB) {
                const char* px = (const char*)(x  + (size_t)gp * 2048) + lane * 256;
                const char* ph = (const char*)(hx + (size_t)gp * 2048) + lane * 256;
                pf_l2(px); pf_l2(px + 128);
                pf_l2(ph); pf_l2(ph + 128);
            }
        }

        // ---- A-fragments via LDG.128: lane reads float4 at col kb*16+4t ----
        // K-slot semantics match the permuted weight rows:
        //   frag[0] = phys cols (4t,4t+1) row grow     -> slots 2t,2t+1
        //   frag[2] = phys cols (4t+2,4t+3) row grow   -> slots 2t+8,2t+9
        //   frag[1],[3] = same cols, row grow+8
        uint32_t xf[2][4][4], hf[2][4][4];
        {
            const float* xb = x  + (size_t)g * 2048;   // 32 rows x 64
            const float* hb = hx + (size_t)g * 2048;
            #pragma unroll
            for (int mb = 0; mb < 2; mb++) {
                const float* xr = xb + (mb * 16 + grow) * 64 + t4;
                const float* hr = hb + (mb * 16 + grow) * 64 + t4;
                #pragma unroll
                for (int kb = 0; kb < 4; kb++) {
                    float4 q0 = *(const float4*)(xr + kb * 16);
                    float4 q8 = *(const float4*)(xr + kb * 16 + 512);   // +8 rows
                    xf[mb][kb][0] = packh2(q0.x, q0.y);
                    xf[mb][kb][2] = packh2(q0.z, q0.w);
                    xf[mb][kb][1] = packh2(q8.x, q8.y);
                    xf[mb][kb][3] = packh2(q8.z, q8.w);
                    float4 p0 = *(const float4*)(hr + kb * 16);
                    float4 p8 = *(const float4*)(hr + kb * 16 + 512);
                    hf[mb][kb][0] = packh2(p0.x, p0.y);
                    hf[mb][kb][2] = packh2(p0.z, p0.w);
                    hf[mb][kb][1] = packh2(p8.x, p8.y);
                    hf[mb][kb][3] = packh2(p8.z, p8.w);
                }
            }
        }

        // ---- r = sig(x@Wir + hx@Whr + br)  (sigma-permuted output space) ----
        float rc[2][8][4];
        #pragma unroll
        for (int nb = 0; nb < 8; nb++) {
            float2 br = *(float2*)(sm + OFF_BIAS + (nb * 8 + q2) * 4);
            #pragma unroll
            for (int mb = 0; mb < 2; mb++) {
                rc[mb][nb][0] = br.x; rc[mb][nb][1] = br.y;
                rc[mb][nb][2] = br.x; rc[mb][nb][3] = br.y;
            }
        }
        gemm2(rc, xf, SB + OFF_W,            laneB);
        gemm2(rc, hf, SB + OFF_W + 1 * 8192, laneB);

        // ---- rh = sigmoid(rc) * hx -> A-fragments (sigma makes this the
        //      same index pattern as before: rc[2kb+..] pairs with hf[kb][..]) ----
        uint32_t rhf[2][4][4];
        #pragma unroll
        for (int mb = 0; mb < 2; mb++) {
            #pragma unroll
            for (int kb = 0; kb < 4; kb++) {
                const float* ce = rc[mb][2 * kb];
                const float* co = rc[mb][2 * kb + 1];
                __half2 s0 = __floats2half2_rn(sigm(ce[0]), sigm(ce[1]));
                __half2 s1 = __floats2half2_rn(sigm(ce[2]), sigm(ce[3]));
                __half2 s2 = __floats2half2_rn(sigm(co[0]), sigm(co[1]));
                __half2 s3 = __floats2half2_rn(sigm(co[2]), sigm(co[3]));
                __half2 m0 = __hmul2(s0, *(const __half2*)&hf[mb][kb][0]);
                __half2 m1 = __hmul2(s1, *(const __half2*)&hf[mb][kb][1]);
                __half2 m2 = __hmul2(s2, *(const __half2*)&hf[mb][kb][2]);
                __half2 m3 = __hmul2(s3, *(const __half2*)&hf[mb][kb][3]);
                rhf[mb][kb][0] = *(uint32_t*)&m0;
                rhf[mb][kb][1] = *(uint32_t*)&m1;
                rhf[mb][kb][2] = *(uint32_t*)&m2;
                rhf[mb][kb][3] = *(uint32_t*)&m3;
            }
        }

        // ---- n = x@Win + rh@Whn + bn (rc dead) ----
        float nc[2][8][4];
        #pragma unroll
        for (int nb = 0; nb < 8; nb++) {
            float2 bn = *(float2*)(sm + OFF_BIAS + 512 + (nb * 8 + q2) * 4);
            #pragma unroll
            for (int mb = 0; mb < 2; mb++) {
                nc[mb][nb][0] = bn.x; nc[mb][nb][1] = bn.y;
                nc[mb][nb][2] = bn.x; nc[mb][nb][3] = bn.y;
            }
        }
        gemm2(nc, xf,  SB + OFF_W + 4 * 8192, laneB);
        gemm2(nc, rhf, SB + OFF_W + 5 * 8192, laneB);

        // ---- z = sig(x@Wiz + hx@Whz + bz) (rhf dead) ----
        float zc[2][8][4];
        #pragma unroll
        for (int nb = 0; nb < 8; nb++) {
            float2 bz = *(float2*)(sm + OFF_BIAS + 256 + (nb * 8 + q2) * 4);
            #pragma unroll
            for (int mb = 0; mb < 2; mb++) {
                zc[mb][nb][0] = bz.x; zc[mb][nb][1] = bz.y;
                zc[mb][nb][2] = bz.x; zc[mb][nb][3] = bz.y;
            }
        }
        gemm2(zc, xf, SB + OFF_W + 2 * 8192, laneB);
        gemm2(zc, hf, SB + OFF_W + 3 * 8192, laneB);

        // ---- epilogue: h = hx + z*(n - hx); lane owns output cols
        //      kb*16+4t..+3 (sigma) -> STG.128; hx straight from hf ----
        #pragma unroll
        for (int mb = 0; mb < 2; mb++) {
            const long rg = g * 32 + mb * 16 + grow;
            #pragma unroll
            for (int kb = 0; kb < 4; kb++) {
                float2 h01 = __half22float2(*(const __half2*)&hf[mb][kb][0]); // row grow, w0 w1
                float2 h23 = __half22float2(*(const __half2*)&hf[mb][kb][2]); // row grow, w2 w3
                float2 g01 = __half22float2(*(const __half2*)&hf[mb][kb][1]); // row grow+8
                float2 g23 = __half22float2(*(const __half2*)&hf[mb][kb][3]);
                const float* ze = zc[mb][2 * kb];
                const float* zo = zc[mb][2 * kb + 1];
                const float* ne = nc[mb][2 * kb];
                const float* no = nc[mb][2 * kb + 1];
                float4 o0, o8;
                o0.x = fmaf(sigm(ze[0]), tanh_ap(ne[0]) - h01.x, h01.x);
                o0.y = fmaf(sigm(ze[1]), tanh_ap(ne[1]) - h01.y, h01.y);
                o0.z = fmaf(sigm(zo[0]), tanh_ap(no[0]) - h23.x, h23.x);
                o0.w = fmaf(sigm(zo[1]), tanh_ap(no[1]) - h23.y, h23.y);
                o8.x = fmaf(sigm(ze[2]), tanh_ap(ne[2]) - g01.x, g01.x);
                o8.y = fmaf(sigm(ze[3]), tanh_ap(ne[3]) - g01.y, g01.y);
                o8.z = fmaf(sigm(zo[2]), tanh_ap(no[2]) - g23.x, g23.x);
                o8.w = fmaf(sigm(zo[3]), tanh_ap(no[3]) - g23.y, g23.y);
                *(float4*)(out + rg * 64 + kb * 16 + t4)       = o0;
                *(float4*)(out + (rg + 8) * 64 + kb * 16 + t4) = o8;
            }
        }
    }
}

extern "C" void kernel_launch(void* const* d_in, const int* in_sizes, int n_in,
                              void* d_out, int out_size) {
    int sms = 0;
    cudaDeviceGetAttribute(&sms, cudaDevAttrMultiProcessorCount, 0);
    if (sms <= 0) sms = 148;
    cudaFuncSetAttribute(gru_kernel, cudaFuncAttributeMaxDynamicSharedMemorySize, SMEM_SZ);
    gru_kernel<<<sms, 256, SMEM_SZ>>>(
        (const float*)d_in[0], (const float*)d_in[1],
        (const float*)d_in[2], (const float*)d_in[3],
        (const float*)d_in[4], (const float*)d_in[5],
        (const float*)d_in[6], (const float*)d_in[7],
        (const float*)d_in[8], (const float*)d_in[9],
        (const float*)d_in[10], (float*)d_out);
}